// round 5
// baseline (speedup 1.0000x reference)
#include <cuda_runtime.h>
#include <math.h>
#include <stdint.h>

#define T_FRAMES 2048
#define EPROJS   1024
#define DUNITS   512
#define JOINT    512
#define ODIM     10000
#define NB       148
#define NT       512
#define NWARP    (NT / 32)

// ---------------- global scratch ----------------
__device__ float  g_hp[T_FRAMES * JOINT];        // encoder-side joint projection
__device__ unsigned long long g_yt[DUNITS];      // epoch-tagged y
__device__ unsigned long long g_dvt[JOINT];      // epoch-tagged dv = Wdec*y
__device__ float4 g_part[2][NB];                 // (max, sumexp, argmax, epoch)

__device__ __forceinline__ unsigned long long ldvol_u64(const unsigned long long* p) {
    unsigned long long v;
    asm volatile("ld.volatile.global.u64 %0, [%1];" : "=l"(v) : "l"(p));
    return v;
}
__device__ __forceinline__ void stvol_u64(unsigned long long* p, unsigned long long v) {
    asm volatile("st.volatile.global.u64 [%0], %1;" :: "l"(p), "l"(v));
}
__device__ __forceinline__ float4 ldvol_f4(const float4* p) {
    float4 v;
    asm volatile("ld.volatile.global.v4.f32 {%0,%1,%2,%3}, [%4];"
                 : "=f"(v.x), "=f"(v.y), "=f"(v.z), "=f"(v.w) : "l"(p));
    return v;
}
__device__ __forceinline__ void stvol_f4(float4* p, float4 v) {
    asm volatile("st.volatile.global.v4.f32 [%0], {%1,%2,%3,%4};"
                 :: "l"(p), "f"(v.x), "f"(v.y), "f"(v.z), "f"(v.w));
}
__device__ __forceinline__ unsigned long long pack_ev(unsigned e, float v) {
    return ((unsigned long long)e << 32) | (unsigned long long)__float_as_uint(v);
}
__device__ __forceinline__ float sigm(float x) { return 1.f / (1.f + expf(-x)); }

// ---------------- hp = h @ W_enc^T + b_enc ----------------
__global__ void hp_kernel(const float* __restrict__ h,
                          const float* __restrict__ Wenc,
                          const float* __restrict__ benc) {
    __shared__ float sh[8 * EPROJS];
    const int tid  = threadIdx.x;
    const int warp = tid >> 5;
    const int lane = tid & 31;
    const size_t t0 = (size_t)blockIdx.x * 8;

    const float4* hsrc = (const float4*)(h + t0 * EPROJS);
    float4* sh4 = (float4*)sh;
    for (int i = tid; i < 8 * EPROJS / 4; i += 256) sh4[i] = hsrc[i];
    __syncthreads();

    const float4* w0 = (const float4*)Wenc;
    for (int pass = 0; pass < 16; pass++) {
        int jb = (pass * 8 + warp) * 4;
        float acc[8][4];
#pragma unroll
        for (int tt = 0; tt < 8; tt++)
#pragma unroll
            for (int jj = 0; jj < 4; jj++) acc[tt][jj] = 0.f;

        for (int qq = 0; qq < 8; qq++) {
            int q = qq * 32 + lane;
            float4 w[4];
#pragma unroll
            for (int jj = 0; jj < 4; jj++)
                w[jj] = w0[(size_t)(jb + jj) * (EPROJS / 4) + q];
#pragma unroll
            for (int tt = 0; tt < 8; tt++) {
                float4 hv = sh4[tt * (EPROJS / 4) + q];
#pragma unroll
                for (int jj = 0; jj < 4; jj++)
                    acc[tt][jj] += hv.x * w[jj].x + hv.y * w[jj].y +
                                   hv.z * w[jj].z + hv.w * w[jj].w;
            }
        }
#pragma unroll
        for (int tt = 0; tt < 8; tt++) {
#pragma unroll
            for (int jj = 0; jj < 4; jj++) {
                float v = acc[tt][jj];
                for (int off = 16; off; off >>= 1)
                    v += __shfl_down_sync(0xffffffffu, v, off);
                if (lane == 0)
                    g_hp[(t0 + tt) * JOINT + jb + jj] = v + benc[jb + jj];
            }
        }
    }
}

// ---------------- smem layout (floats) ----------------
#define SM_WOUT   0
#define SM_WHH    (SM_WOUT + 68 * JOINT)
#define SM_WIH    (SM_WHH + 16 * DUNITS)
#define SM_WDEC   (SM_WIH + 16 * DUNITS)
#define SM_Y      (SM_WDEC + 4 * DUNITS)
#define SM_DV     (SM_Y + DUNITS)
#define SM_Z      (SM_DV + JOINT)          /* also reused for ey */
#define SM_HP     (SM_Z + JOINT)
#define SM_BO     (SM_HP + JOINT)
#define SM_BS     (SM_BO + 68)
#define SM_GH     (SM_BS + 16)
#define SM_GT     (SM_GH + 16)
#define SM_C      (SM_GT + 16)
#define SM_BC     (SM_C + 4)
#define SM_WM     (SM_BC + 4)
#define SM_WA     (SM_WM + NWARP)
#define SM_WS     (SM_WA + NWARP)
#define SM_PM     (SM_WS + NWARP)
#define SM_PS     (SM_PM + NB)
#define SM_PA     (SM_PS + NB)
#define SM_TOTAL_FLOATS (SM_PA + NB)

__global__ void __launch_bounds__(NT, 1)
decode_kernel(const float* __restrict__ embed,
              const float* __restrict__ Wih, const float* __restrict__ Whh,
              const float* __restrict__ bih, const float* __restrict__ bhh,
              const float* __restrict__ Wdec, const float* __restrict__ Wout,
              const float* __restrict__ bout,
              float* __restrict__ out, int out_size) {
    extern __shared__ float sm[];
    const int b    = blockIdx.x;
    const int tid  = threadIdx.x;
    const int warp = tid >> 5;
    const int lane = tid & 31;

    const int r0 = (b * ODIM) / NB, r1 = ((b + 1) * ODIM) / NB, nr = r1 - r0;
    const int k0 = (b * DUNITS) / NB, k1 = ((b + 1) * DUNITS) / NB, nk = k1 - k0;

    float* sWout = sm + SM_WOUT;
    float* sWhh  = sm + SM_WHH;
    float* sWih  = sm + SM_WIH;
    float* sWdec = sm + SM_WDEC;
    float* s_y   = sm + SM_Y;
    float* s_dv  = sm + SM_DV;
    float* s_z   = sm + SM_Z;     // z during logits, ey during LSTM
    float* s_hp  = sm + SM_HP;
    float* s_bo  = sm + SM_BO;
    float* s_bs  = sm + SM_BS;
    float* s_gh  = sm + SM_GH;
    float* s_gt  = sm + SM_GT;
    float* s_c   = sm + SM_C;
    float* s_bc  = sm + SM_BC;
    float* s_wm  = sm + SM_WM;
    int*   s_wa  = (int*)(sm + SM_WA);
    float* s_ws  = sm + SM_WS;
    float* s_pm  = sm + SM_PM;
    float* s_ps  = sm + SM_PS;
    int*   s_pa  = (int*)(sm + SM_PA);

    // ---- load weights into shared (resident for entire decode) ----
    {
        const float4* src = (const float4*)(Wout + (size_t)r0 * JOINT);
        float4* dst = (float4*)sWout;
        for (int i = tid; i < nr * (JOINT / 4); i += NT) dst[i] = src[i];
    }
    for (int i = tid; i < nr; i += NT) s_bo[i] = bout[r0 + i];
    {
        const int ng = 4 * nk;
        for (int i = tid; i < ng * (DUNITS / 4); i += NT) {
            int lr = i / (DUNITS / 4), x = i % (DUNITS / 4);
            int gi = lr & 3, ki = lr >> 2;
            size_t G = (size_t)(gi * DUNITS + k0 + ki);
            ((float4*)sWhh)[i] = ((const float4*)(Whh + G * DUNITS))[x];
            ((float4*)sWih)[i] = ((const float4*)(Wih + G * DUNITS))[x];
        }
        for (int i = tid; i < ng; i += NT) {
            int gi = i & 3, ki = i >> 2;
            int G = gi * DUNITS + k0 + ki;
            s_bs[i] = bih[G] + bhh[G];
        }
    }
    {
        const float4* src = (const float4*)(Wdec + (size_t)k0 * DUNITS);
        float4* dst = (float4*)sWdec;
        for (int i = tid; i < nk * (DUNITS / 4); i += NT) dst[i] = src[i];
    }
    __syncthreads();

    // ---- prologue: y0, publish tagged with epoch 1 ----
    unsigned e = 1;
    if (warp == 0 && lane < nk) {
        float gi_ = s_bs[4 * lane + 0];
        float gg_ = s_bs[4 * lane + 2];
        float go_ = s_bs[4 * lane + 3];
        float c  = sigm(gi_) * tanhf(gg_);
        float yv = sigm(go_) * tanhf(c);
        s_c[lane] = c;
        stvol_u64(&g_yt[k0 + lane], pack_ev(1u, yv));
    }
    {   // all threads poll their y element
        unsigned long long v;
        do { v = ldvol_u64(&g_yt[tid]); } while ((unsigned)(v >> 32) != 1u);
        s_y[tid] = __uint_as_float((unsigned)v);
    }
    __syncthreads();
    // dv rows (publish) + gh rows (local)
    for (int it = warp; it < 5 * nk; it += NWARP) {
        const float4* r4 = (const float4*)((it < nk) ? (sWdec + it * DUNITS)
                                                     : (sWhh + (it - nk) * DUNITS));
        const float4* y4 = (const float4*)s_y;
        float acc = 0.f;
#pragma unroll
        for (int q = 0; q < 4; q++) {
            float4 w = r4[lane + 32 * q], yv = y4[lane + 32 * q];
            acc += w.x * yv.x + w.y * yv.y + w.z * yv.z + w.w * yv.w;
        }
        for (int off = 16; off; off >>= 1)
            acc += __shfl_down_sync(0xffffffffu, acc, off);
        if (lane == 0) {
            if (it < nk) stvol_u64(&g_dvt[k0 + it], pack_ev(1u, acc));
            else         s_gh[it - nk] = acc;
        }
    }
    {   // poll full dv
        unsigned long long v;
        do { v = ldvol_u64(&g_dvt[tid]); } while ((unsigned)(v >> 32) != 1u);
        s_dv[tid] = __uint_as_float((unsigned)v);
    }
    s_hp[tid] = g_hp[tid];   // hp row 0
    __syncthreads();

    float score = 0.f;

    for (int t = 0; t < T_FRAMES; t++) {
        const int par = t & 1;

        // ===== z fully local: z = tanh(hp_t + dv) =====
        s_z[tid] = tanhf(s_hp[tid] + s_dv[tid]);
        __syncthreads();

        float4 zr[4];
#pragma unroll
        for (int q = 0; q < 4; q++) zr[q] = ((const float4*)s_z)[lane + 32 * q];

        // prefetch next hp row (landed into smem after logits)
        float hpn = (t + 1 < T_FRAMES)
                        ? __ldg(&g_hp[(size_t)(t + 1) * JOINT + tid]) : 0.f;

        // ===== logits rows =====
        float accv[5];
        int rcount = 0;
        for (int lr = warp, i = 0; lr < nr; lr += NWARP, i++) {
            const float4* r4 = (const float4*)(sWout + lr * JOINT);
            float a = 0.f;
#pragma unroll
            for (int q = 0; q < 4; q++) {
                float4 w = r4[lane + 32 * q];
                a += w.x * zr[q].x + w.y * zr[q].y + w.z * zr[q].z + w.w * zr[q].w;
            }
            accv[i] = a;
            rcount = i + 1;
        }
        s_hp[tid] = hpn;
#pragma unroll
        for (int i = 0; i < 5; i++) {
            float a = (i < rcount) ? accv[i] : 0.f;
            a += __shfl_down_sync(0xffffffffu, a, 16);
            a += __shfl_down_sync(0xffffffffu, a, 8);
            a += __shfl_down_sync(0xffffffffu, a, 4);
            a += __shfl_down_sync(0xffffffffu, a, 2);
            a += __shfl_down_sync(0xffffffffu, a, 1);
            accv[i] = a;
        }

        // per-warp online softmax stats
        if (lane == 0) {
            float m = -INFINITY, s = 0.f;
            int a = 0x7fffffff;
#pragma unroll
            for (int i = 0; i < 5; i++) {
                if (i < rcount) {
                    int lr = warp + NWARP * i;
                    float l = accv[i] + s_bo[lr];
                    if (l > m) { s = s * __expf(m - l) + 1.f; m = l; a = r0 + lr; }
                    else       { s += __expf(l - m); }
                }
            }
            s_wm[warp] = m; s_wa[warp] = a; s_ws[warp] = s;
        }
        __syncthreads();

        // warp0: block merge + publish (single 16B tagged store)
        if (warp == 0) {
            float mo = (lane < NWARP) ? s_wm[lane] : -INFINITY;
            float so = (lane < NWARP) ? s_ws[lane] : 0.f;
            int   ao = (lane < NWARP) ? s_wa[lane] : 0x7fffffff;
            float m = mo; int a = ao;
#pragma unroll
            for (int off = 16; off; off >>= 1) {
                float m2 = __shfl_xor_sync(0xffffffffu, m, off);
                int   a2 = __shfl_xor_sync(0xffffffffu, a, off);
                if (m2 > m || (m2 == m && a2 < a)) { m = m2; a = a2; }
            }
            float sc = (lane < NWARP) ? so * __expf(mo - m) : 0.f;
#pragma unroll
            for (int off = 16; off; off >>= 1)
                sc += __shfl_xor_sync(0xffffffffu, sc, off);
            if (lane == 0)
                stvol_f4(&g_part[par][b],
                         make_float4(m, sc, __int_as_float(a), (float)(t + 1)));
        }

        // ===== poll all 148 partials (data-as-flag, parallel threads) =====
        if (tid < NB) {
            const float tgt = (float)(t + 1);
            float4 p;
            do { p = ldvol_f4(&g_part[par][tid]); } while (p.w != tgt);
            s_pm[tid] = p.x; s_ps[tid] = p.y; s_pa[tid] = __float_as_int(p.z);
        }
        __syncthreads();

        // warp0: global merge over smem partials
        if (warp == 0) {
            float mi[5], si[5]; int ai[5];
#pragma unroll
            for (int i = 0; i < 5; i++) {
                int idx = lane + 32 * i;
                bool vld = idx < NB;
                mi[i] = vld ? s_pm[idx] : -INFINITY;
                si[i] = vld ? s_ps[idx] : 0.f;
                ai[i] = vld ? s_pa[idx] : 0x7fffffff;
            }
            float m = mi[0]; int a = ai[0];
#pragma unroll
            for (int i = 1; i < 5; i++)
                if (mi[i] > m || (mi[i] == m && ai[i] < a)) { m = mi[i]; a = ai[i]; }
#pragma unroll
            for (int off = 16; off; off >>= 1) {
                float m2 = __shfl_xor_sync(0xffffffffu, m, off);
                int   a2 = __shfl_xor_sync(0xffffffffu, a, off);
                if (m2 > m || (m2 == m && a2 < a)) { m = m2; a = a2; }
            }
            float sc = 0.f;
#pragma unroll
            for (int i = 0; i < 5; i++) sc += si[i] * __expf(mi[i] - m);
#pragma unroll
            for (int off = 16; off; off >>= 1)
                sc += __shfl_xor_sync(0xffffffffu, sc, off);
            if (lane == 0) {
                s_bc[0] = __int_as_float(a);
                s_bc[1] = -__logf(sc);
            }
        }
        __syncthreads();

        const int   pred    = __float_as_int(s_bc[0]);
        const float logp    = s_bc[1];
        const bool  emitted = (pred != 0);

        if (b == 0 && tid == 0) {
            if (t < out_size) out[t] = emitted ? (float)pred : 0.0f;
            if (emitted) score += logp;
        }

        // ===== emission: LSTM + y handoff + dv/gh recompute =====
        if (emitted) {
            e++;
            s_z[tid] = __ldg(&embed[(size_t)pred * DUNITS + tid]);  // ey
            __syncthreads();

            for (int lr = warp; lr < 4 * nk; lr += NWARP) {
                const float4* r4 = (const float4*)(sWih + lr * DUNITS);
                const float4* e4 = (const float4*)s_z;
                float acc = 0.f;
#pragma unroll
                for (int q = 0; q < 4; q++) {
                    float4 w = r4[lane + 32 * q], ev = e4[lane + 32 * q];
                    acc += w.x * ev.x + w.y * ev.y + w.z * ev.z + w.w * ev.w;
                }
                for (int off = 16; off; off >>= 1)
                    acc += __shfl_down_sync(0xffffffffu, acc, off);
                if (lane == 0) s_gt[lr] = s_bs[lr] + s_gh[lr] + acc;
            }
            __syncthreads();

            if (warp == 0 && lane < nk) {
                float gi_ = s_gt[4 * lane + 0], gf_ = s_gt[4 * lane + 1];
                float gg_ = s_gt[4 * lane + 2], go_ = s_gt[4 * lane + 3];
                float c  = s_c[lane];
                float cn = sigm(gf_) * c + sigm(gi_) * tanhf(gg_);
                float yn = sigm(go_) * tanhf(cn);
                s_c[lane] = cn;
                stvol_u64(&g_yt[k0 + lane], pack_ev(e, yn));
            }
            {   // poll full new y
                unsigned long long v;
                do { v = ldvol_u64(&g_yt[tid]); } while ((unsigned)(v >> 32) != e);
                s_y[tid] = __uint_as_float((unsigned)v);
            }
            __syncthreads();

            // dv rows (publish) + gh rows (local refresh)
            for (int it = warp; it < 5 * nk; it += NWARP) {
                const float4* r4 = (const float4*)((it < nk)
                                    ? (sWdec + it * DUNITS)
                                    : (sWhh + (it - nk) * DUNITS));
                const float4* y4 = (const float4*)s_y;
                float acc = 0.f;
#pragma unroll
                for (int q = 0; q < 4; q++) {
                    float4 w = r4[lane + 32 * q], yv = y4[lane + 32 * q];
                    acc += w.x * yv.x + w.y * yv.y + w.z * yv.z + w.w * yv.w;
                }
                for (int off = 16; off; off >>= 1)
                    acc += __shfl_down_sync(0xffffffffu, acc, off);
                if (lane == 0) {
                    if (it < nk) stvol_u64(&g_dvt[k0 + it], pack_ev(e, acc));
                    else         s_gh[it - nk] = acc;
                }
            }
            {   // poll full new dv
                unsigned long long v;
                do { v = ldvol_u64(&g_dvt[tid]); } while ((unsigned)(v >> 32) != e);
                s_dv[tid] = __uint_as_float((unsigned)v);
            }
            __syncthreads();
        }
    }

    if (b == 0) {
        if (tid == 0 && out_size > T_FRAMES) out[T_FRAMES] = score;
        for (int i = T_FRAMES + 1 + tid; i < out_size; i += NT) out[i] = 0.f;
    }
}

// ---------------- launch ----------------
extern "C" void kernel_launch(void* const* d_in, const int* in_sizes, int n_in,
                              void* d_out, int out_size) {
    (void)in_sizes; (void)n_in;
    const float* h     = (const float*)d_in[0];
    const float* embed = (const float*)d_in[1];
    const float* Wih   = (const float*)d_in[2];
    const float* Whh   = (const float*)d_in[3];
    const float* bih   = (const float*)d_in[4];
    const float* bhh   = (const float*)d_in[5];
    const float* Wenc  = (const float*)d_in[6];
    const float* benc  = (const float*)d_in[7];
    const float* Wdec  = (const float*)d_in[8];
    const float* Wout  = (const float*)d_in[9];
    const float* bout  = (const float*)d_in[10];
    float* out = (float*)d_out;

    const int smem_bytes = SM_TOTAL_FLOATS * (int)sizeof(float);
    cudaFuncSetAttribute(decode_kernel,
                         cudaFuncAttributeMaxDynamicSharedMemorySize, smem_bytes);

    hp_kernel<<<T_FRAMES / 8, 256>>>(h, Wenc, benc);
    decode_kernel<<<NB, NT, smem_bytes>>>(embed, Wih, Whh, bih, bhh,
                                          Wdec, Wout, bout, out, out_size);
}

// round 6
// speedup vs baseline: 1.9010x; 1.9010x over previous
#include <cuda_runtime.h>
#include <math.h>
#include <stdint.h>

#define T_FRAMES 2048
#define EPROJS   1024
#define DUNITS   512
#define JOINT    512
#define ODIM     10000
#define NB       148
#define NT       512
#define NWARP    (NT / 32)

// ---------------- global scratch ----------------
__device__ float  g_hp[T_FRAMES * JOINT];   // encoder-side joint projection
__device__ float  g_yv[DUNITS];             // prediction-net state (per emission epoch)
__device__ float  g_dv[JOINT];              // dv = Wdec*y (per emission epoch)
__device__ float4 g_part[2][NB];            // (max, sumexp, argmax-bits, unused)
__device__ __align__(128) unsigned g_cp;    // partial arrivals: NB per step
__device__ __align__(128) unsigned g_cy;    // y arrivals: NB per emission epoch
__device__ __align__(128) unsigned g_cdv;   // dv arrivals: NB per emission epoch

__device__ __forceinline__ void red_release(unsigned* p) {
    asm volatile("red.release.gpu.global.add.u32 [%0], 1;" :: "l"(p) : "memory");
}
__device__ __forceinline__ unsigned ld_acquire(unsigned* p) {
    unsigned v;
    asm volatile("ld.acquire.gpu.global.u32 %0, [%1];" : "=r"(v) : "l"(p) : "memory");
    return v;
}
__device__ __forceinline__ float sigm(float x) { return 1.f / (1.f + expf(-x)); }

// ---------------- hp = h @ W_enc^T + b_enc ----------------
__global__ void hp_kernel(const float* __restrict__ h,
                          const float* __restrict__ Wenc,
                          const float* __restrict__ benc) {
    if (blockIdx.x == 0 && threadIdx.x == 0) { g_cp = 0u; g_cy = 0u; g_cdv = 0u; }

    __shared__ float sh[8 * EPROJS];
    const int tid  = threadIdx.x;
    const int warp = tid >> 5;
    const int lane = tid & 31;
    const size_t t0 = (size_t)blockIdx.x * 8;

    const float4* hsrc = (const float4*)(h + t0 * EPROJS);
    float4* sh4 = (float4*)sh;
    for (int i = tid; i < 8 * EPROJS / 4; i += 256) sh4[i] = hsrc[i];
    __syncthreads();

    const float4* w0 = (const float4*)Wenc;
    for (int pass = 0; pass < 16; pass++) {
        int jb = (pass * 8 + warp) * 4;
        float acc[8][4];
#pragma unroll
        for (int tt = 0; tt < 8; tt++)
#pragma unroll
            for (int jj = 0; jj < 4; jj++) acc[tt][jj] = 0.f;

        for (int qq = 0; qq < 8; qq++) {
            int q = qq * 32 + lane;
            float4 w[4];
#pragma unroll
            for (int jj = 0; jj < 4; jj++)
                w[jj] = w0[(size_t)(jb + jj) * (EPROJS / 4) + q];
#pragma unroll
            for (int tt = 0; tt < 8; tt++) {
                float4 hv = sh4[tt * (EPROJS / 4) + q];
#pragma unroll
                for (int jj = 0; jj < 4; jj++)
                    acc[tt][jj] += hv.x * w[jj].x + hv.y * w[jj].y +
                                   hv.z * w[jj].z + hv.w * w[jj].w;
            }
        }
#pragma unroll
        for (int tt = 0; tt < 8; tt++) {
#pragma unroll
            for (int jj = 0; jj < 4; jj++) {
                float v = acc[tt][jj];
                for (int off = 16; off; off >>= 1)
                    v += __shfl_down_sync(0xffffffffu, v, off);
                if (lane == 0)
                    g_hp[(t0 + tt) * JOINT + jb + jj] = v + benc[jb + jj];
            }
        }
    }
}

// ---------------- smem layout (floats) ----------------
#define SM_WOUT   0
#define SM_WHH    (SM_WOUT + 68 * JOINT)
#define SM_WIH    (SM_WHH + 16 * DUNITS)
#define SM_WDEC   (SM_WIH + 16 * DUNITS)
#define SM_Y      (SM_WDEC + 4 * DUNITS)
#define SM_DV     (SM_Y + DUNITS)
#define SM_Z      (SM_DV + JOINT)          /* reused as ey during LSTM */
#define SM_HP     (SM_Z + JOINT)
#define SM_BO     (SM_HP + JOINT)
#define SM_BS     (SM_BO + 68)
#define SM_GH     (SM_BS + 16)
#define SM_GT     (SM_GH + 16)
#define SM_C      (SM_GT + 16)
#define SM_BC     (SM_C + 4)
#define SM_WM     (SM_BC + 4)
#define SM_WA     (SM_WM + NWARP)
#define SM_WS     (SM_WA + NWARP)
#define SM_PM     (SM_WS + NWARP)
#define SM_PS     (SM_PM + NB)
#define SM_PA     (SM_PS + NB)
#define SM_TOTAL_FLOATS (SM_PA + NB)

__global__ void __launch_bounds__(NT, 1)
decode_kernel(const float* __restrict__ embed,
              const float* __restrict__ Wih, const float* __restrict__ Whh,
              const float* __restrict__ bih, const float* __restrict__ bhh,
              const float* __restrict__ Wdec, const float* __restrict__ Wout,
              const float* __restrict__ bout,
              float* __restrict__ out, int out_size) {
    extern __shared__ float sm[];
    const int b    = blockIdx.x;
    const int tid  = threadIdx.x;
    const int warp = tid >> 5;
    const int lane = tid & 31;

    const int r0 = (b * ODIM) / NB, r1 = ((b + 1) * ODIM) / NB, nr = r1 - r0;
    const int k0 = (b * DUNITS) / NB, k1 = ((b + 1) * DUNITS) / NB, nk = k1 - k0;

    float* sWout = sm + SM_WOUT;
    float* sWhh  = sm + SM_WHH;
    float* sWih  = sm + SM_WIH;
    float* sWdec = sm + SM_WDEC;
    float* s_y   = sm + SM_Y;
    float* s_dv  = sm + SM_DV;
    float* s_z   = sm + SM_Z;
    float* s_hp  = sm + SM_HP;
    float* s_bo  = sm + SM_BO;
    float* s_bs  = sm + SM_BS;
    float* s_gh  = sm + SM_GH;
    float* s_gt  = sm + SM_GT;
    float* s_c   = sm + SM_C;
    float* s_bc  = sm + SM_BC;
    float* s_wm  = sm + SM_WM;
    int*   s_wa  = (int*)(sm + SM_WA);
    float* s_ws  = sm + SM_WS;
    float* s_pm  = sm + SM_PM;
    float* s_ps  = sm + SM_PS;
    int*   s_pa  = (int*)(sm + SM_PA);

    // ---- load weights into shared (resident for entire decode) ----
    {
        const float4* src = (const float4*)(Wout + (size_t)r0 * JOINT);
        float4* dst = (float4*)sWout;
        for (int i = tid; i < nr * (JOINT / 4); i += NT) dst[i] = src[i];
    }
    for (int i = tid; i < nr; i += NT) s_bo[i] = bout[r0 + i];
    {
        const int ng = 4 * nk;
        for (int i = tid; i < ng * (DUNITS / 4); i += NT) {
            int lr = i / (DUNITS / 4), x = i % (DUNITS / 4);
            int gi = lr & 3, ki = lr >> 2;
            size_t G = (size_t)(gi * DUNITS + k0 + ki);
            ((float4*)sWhh)[i] = ((const float4*)(Whh + G * DUNITS))[x];
            ((float4*)sWih)[i] = ((const float4*)(Wih + G * DUNITS))[x];
        }
        for (int i = tid; i < ng; i += NT) {
            int gi = i & 3, ki = i >> 2;
            int G = gi * DUNITS + k0 + ki;
            s_bs[i] = bih[G] + bhh[G];
        }
    }
    {
        const float4* src = (const float4*)(Wdec + (size_t)k0 * DUNITS);
        float4* dst = (float4*)sWdec;
        for (int i = tid; i < nk * (DUNITS / 4); i += NT) dst[i] = src[i];
    }
    __syncthreads();

    unsigned e = 1;   // emission epoch (prologue = 1)

    // ---- prologue: y0 from zero input / zero state ----
    if (warp == 0) {
        if (lane < nk) {
            float gi_ = s_bs[4 * lane + 0];
            float gg_ = s_bs[4 * lane + 2];
            float go_ = s_bs[4 * lane + 3];
            float c  = sigm(gi_) * tanhf(gg_);
            float yv = sigm(go_) * tanhf(c);
            s_c[lane] = c;
            g_yv[k0 + lane] = yv;
        }
        __syncwarp();
        if (lane == 0) red_release(&g_cy);
    }
    if (tid == 0) { while (ld_acquire(&g_cy) < NB * e) {} }
    __syncthreads();
    s_y[tid] = __ldcv(&g_yv[tid]);
    __syncthreads();

    // dv rows (publish, warps < nk) -----------------------------------------
    if (warp < nk) {
        const float4* r4 = (const float4*)(sWdec + warp * DUNITS);
        const float4* y4 = (const float4*)s_y;
        float acc = 0.f;
#pragma unroll
        for (int q = 0; q < 4; q++) {
            float4 w = r4[lane + 32 * q], yv = y4[lane + 32 * q];
            acc += w.x * yv.x + w.y * yv.y + w.z * yv.z + w.w * yv.w;
        }
        for (int off = 16; off; off >>= 1)
            acc += __shfl_down_sync(0xffffffffu, acc, off);
        if (lane == 0) g_dv[k0 + warp] = acc;
        asm volatile("bar.sync 1, %0;" :: "r"(nk * 32) : "memory");
        if (warp == 0 && lane == 0) red_release(&g_cdv);
    }
    // gh rows (local)
    for (int g = warp; g < 4 * nk; g += NWARP) {
        const float4* r4 = (const float4*)(sWhh + g * DUNITS);
        const float4* y4 = (const float4*)s_y;
        float acc = 0.f;
#pragma unroll
        for (int q = 0; q < 4; q++) {
            float4 w = r4[lane + 32 * q], yv = y4[lane + 32 * q];
            acc += w.x * yv.x + w.y * yv.y + w.z * yv.z + w.w * yv.w;
        }
        for (int off = 16; off; off >>= 1)
            acc += __shfl_down_sync(0xffffffffu, acc, off);
        if (lane == 0) s_gh[g] = acc;
    }
    if (tid == 0) { while (ld_acquire(&g_cdv) < NB * e) {} }
    __syncthreads();
    s_dv[tid] = __ldcv(&g_dv[tid]);
    s_hp[tid] = g_hp[tid];   // hp row 0
    __syncthreads();

    float score = 0.f;

    for (int t = 0; t < T_FRAMES; t++) {
        const int par = t & 1;

        // ===== z fully local: z = tanh(hp_t + dv) =====
        s_z[tid] = tanhf(s_hp[tid] + s_dv[tid]);
        __syncthreads();

        float4 zr[4];
#pragma unroll
        for (int q = 0; q < 4; q++) zr[q] = ((const float4*)s_z)[lane + 32 * q];

        // prefetch next hp row (landed into smem after logits)
        float hpn = (t + 1 < T_FRAMES)
                        ? __ldg(&g_hp[(size_t)(t + 1) * JOINT + tid]) : 0.f;

        // ===== logits rows =====
        float accv[5];
        int rcount = 0;
        for (int lr = warp, i = 0; lr < nr; lr += NWARP, i++) {
            const float4* r4 = (const float4*)(sWout + lr * JOINT);
            float a = 0.f;
#pragma unroll
            for (int q = 0; q < 4; q++) {
                float4 w = r4[lane + 32 * q];
                a += w.x * zr[q].x + w.y * zr[q].y + w.z * zr[q].z + w.w * zr[q].w;
            }
            accv[i] = a;
            rcount = i + 1;
        }
        s_hp[tid] = hpn;
#pragma unroll
        for (int i = 0; i < 5; i++) {
            float a = (i < rcount) ? accv[i] : 0.f;
            a += __shfl_down_sync(0xffffffffu, a, 16);
            a += __shfl_down_sync(0xffffffffu, a, 8);
            a += __shfl_down_sync(0xffffffffu, a, 4);
            a += __shfl_down_sync(0xffffffffu, a, 2);
            a += __shfl_down_sync(0xffffffffu, a, 1);
            accv[i] = a;
        }

        // per-warp online softmax stats
        if (lane == 0) {
            float m = -INFINITY, s = 0.f;
            int a = 0x7fffffff;
#pragma unroll
            for (int i = 0; i < 5; i++) {
                if (i < rcount) {
                    int lr = warp + NWARP * i;
                    float l = accv[i] + s_bo[lr];
                    if (l > m) { s = s * __expf(m - l) + 1.f; m = l; a = r0 + lr; }
                    else       { s += __expf(l - m); }
                }
            }
            s_wm[warp] = m; s_wa[warp] = a; s_ws[warp] = s;
        }
        __syncthreads();

        // warp0: block merge + publish partial + release
        if (warp == 0) {
            float mo = (lane < NWARP) ? s_wm[lane] : -INFINITY;
            float so = (lane < NWARP) ? s_ws[lane] : 0.f;
            int   ao = (lane < NWARP) ? s_wa[lane] : 0x7fffffff;
            float m = mo; int a = ao;
#pragma unroll
            for (int off = 16; off; off >>= 1) {
                float m2 = __shfl_xor_sync(0xffffffffu, m, off);
                int   a2 = __shfl_xor_sync(0xffffffffu, a, off);
                if (m2 > m || (m2 == m && a2 < a)) { m = m2; a = a2; }
            }
            float sc = (lane < NWARP) ? so * __expf(mo - m) : 0.f;
#pragma unroll
            for (int off = 16; off; off >>= 1)
                sc += __shfl_xor_sync(0xffffffffu, sc, off);
            if (lane == 0) {
                g_part[par][b] = make_float4(m, sc, __int_as_float(a), 0.f);
                red_release(&g_cp);
            }
        }

        // ===== wait partials (single poller), bulk read once =====
        if (tid == 0) {
            const unsigned tgt = (unsigned)NB * (unsigned)(t + 1);
            while (ld_acquire(&g_cp) < tgt) {}
        }
        __syncthreads();
        if (tid < NB) {
            float4 p = __ldcv(&g_part[par][tid]);
            s_pm[tid] = p.x; s_ps[tid] = p.y; s_pa[tid] = __float_as_int(p.z);
        }
        __syncthreads();

        // warp0: global merge over smem partials
        if (warp == 0) {
            float mi[5], si[5]; int ai[5];
#pragma unroll
            for (int i = 0; i < 5; i++) {
                int idx = lane + 32 * i;
                bool vld = idx < NB;
                mi[i] = vld ? s_pm[idx] : -INFINITY;
                si[i] = vld ? s_ps[idx] : 0.f;
                ai[i] = vld ? s_pa[idx] : 0x7fffffff;
            }
            float m = mi[0]; int a = ai[0];
#pragma unroll
            for (int i = 1; i < 5; i++)
                if (mi[i] > m || (mi[i] == m && ai[i] < a)) { m = mi[i]; a = ai[i]; }
#pragma unroll
            for (int off = 16; off; off >>= 1) {
                float m2 = __shfl_xor_sync(0xffffffffu, m, off);
                int   a2 = __shfl_xor_sync(0xffffffffu, a, off);
                if (m2 > m || (m2 == m && a2 < a)) { m = m2; a = a2; }
            }
            float sc = 0.f;
#pragma unroll
            for (int i = 0; i < 5; i++) sc += si[i] * __expf(mi[i] - m);
#pragma unroll
            for (int off = 16; off; off >>= 1)
                sc += __shfl_xor_sync(0xffffffffu, sc, off);
            if (lane == 0) {
                s_bc[0] = __int_as_float(a);
                s_bc[1] = -__logf(sc);
            }
        }
        __syncthreads();

        const int   pred    = __float_as_int(s_bc[0]);
        const float logp    = s_bc[1];
        const bool  emitted = (pred != 0);

        if (b == 0 && tid == 0) {
            if (t < out_size) out[t] = emitted ? (float)pred : 0.0f;
            if (emitted) score += logp;
        }

        // ===== emission: LSTM + y handoff + dv/gh refresh =====
        if (emitted) {
            e++;
            s_z[tid] = __ldg(&embed[(size_t)pred * DUNITS + tid]);  // ey
            __syncthreads();

            for (int lr = warp; lr < 4 * nk; lr += NWARP) {
                const float4* r4 = (const float4*)(sWih + lr * DUNITS);
                const float4* e4 = (const float4*)s_z;
                float acc = 0.f;
#pragma unroll
                for (int q = 0; q < 4; q++) {
                    float4 w = r4[lane + 32 * q], ev = e4[lane + 32 * q];
                    acc += w.x * ev.x + w.y * ev.y + w.z * ev.z + w.w * ev.w;
                }
                for (int off = 16; off; off >>= 1)
                    acc += __shfl_down_sync(0xffffffffu, acc, off);
                if (lane == 0) s_gt[lr] = s_bs[lr] + s_gh[lr] + acc;
            }
            __syncthreads();

            if (warp == 0) {
                if (lane < nk) {
                    float gi_ = s_gt[4 * lane + 0], gf_ = s_gt[4 * lane + 1];
                    float gg_ = s_gt[4 * lane + 2], go_ = s_gt[4 * lane + 3];
                    float c  = s_c[lane];
                    float cn = sigm(gf_) * c + sigm(gi_) * tanhf(gg_);
                    float yn = sigm(go_) * tanhf(cn);
                    s_c[lane] = cn;
                    g_yv[k0 + lane] = yn;
                }
                __syncwarp();
                if (lane == 0) red_release(&g_cy);
            }
            if (tid == 0) { while (ld_acquire(&g_cy) < NB * e) {} }
            __syncthreads();
            s_y[tid] = __ldcv(&g_yv[tid]);
            __syncthreads();

            // dv rows (publish, warps < nk)
            if (warp < nk) {
                const float4* r4 = (const float4*)(sWdec + warp * DUNITS);
                const float4* y4 = (const float4*)s_y;
                float acc = 0.f;
#pragma unroll
                for (int q = 0; q < 4; q++) {
                    float4 w = r4[lane + 32 * q], yv = y4[lane + 32 * q];
                    acc += w.x * yv.x + w.y * yv.y + w.z * yv.z + w.w * yv.w;
                }
                for (int off = 16; off; off >>= 1)
                    acc += __shfl_down_sync(0xffffffffu, acc, off);
                if (lane == 0) g_dv[k0 + warp] = acc;
                asm volatile("bar.sync 1, %0;" :: "r"(nk * 32) : "memory");
                if (warp == 0 && lane == 0) red_release(&g_cdv);
            }
            // gh rows (local refresh for next emission)
            for (int g = warp; g < 4 * nk; g += NWARP) {
                const float4* r4 = (const float4*)(sWhh + g * DUNITS);
                const float4* y4 = (const float4*)s_y;
                float acc = 0.f;
#pragma unroll
                for (int q = 0; q < 4; q++) {
                    float4 w = r4[lane + 32 * q], yv = y4[lane + 32 * q];
                    acc += w.x * yv.x + w.y * yv.y + w.z * yv.z + w.w * yv.w;
                }
                for (int off = 16; off; off >>= 1)
                    acc += __shfl_down_sync(0xffffffffu, acc, off);
                if (lane == 0) s_gh[g] = acc;
            }
            if (tid == 0) { while (ld_acquire(&g_cdv) < NB * e) {} }
            __syncthreads();
            s_dv[tid] = __ldcv(&g_dv[tid]);
            __syncthreads();
        }
    }

    if (b == 0) {
        if (tid == 0 && out_size > T_FRAMES) out[T_FRAMES] = score;
        for (int i = T_FRAMES + 1 + tid; i < out_size; i += NT) out[i] = 0.f;
    }
}

// ---------------- launch ----------------
extern "C" void kernel_launch(void* const* d_in, const int* in_sizes, int n_in,
                              void* d_out, int out_size) {
    (void)in_sizes; (void)n_in;
    const float* h     = (const float*)d_in[0];
    const float* embed = (const float*)d_in[1];
    const float* Wih   = (const float*)d_in[2];
    const float* Whh   = (const float*)d_in[3];
    const float* bih   = (const float*)d_in[4];
    const float* bhh   = (const float*)d_in[5];
    const float* Wenc  = (const float*)d_in[6];
    const float* benc  = (const float*)d_in[7];
    const float* Wdec  = (const float*)d_in[8];
    const float* Wout  = (const float*)d_in[9];
    const float* bout  = (const float*)d_in[10];
    float* out = (float*)d_out;

    const int smem_bytes = SM_TOTAL_FLOATS * (int)sizeof(float);
    cudaFuncSetAttribute(decode_kernel,
                         cudaFuncAttributeMaxDynamicSharedMemorySize, smem_bytes);

    hp_kernel<<<T_FRAMES / 8, 256>>>(h, Wenc, benc);
    decode_kernel<<<NB, NT, smem_bytes>>>(embed, Wih, Whh, bih, bhh,
                                          Wdec, Wout, bout, out, out_size);
}